// round 12
// baseline (speedup 1.0000x reference)
#include <cuda_runtime.h>
#include <cuda_fp16.h>
#include <math.h>
#include <stdint.h>

#define BATCH 4096
#define SEQ 14
#define MTOK (BATCH * SEQ)          /* 57344 tokens */
#define CIN 512
#define PDIM 1024
#define EMBN 768                    /* P - 256 */
#define POSN 256
#define HEADS 8
#define DHEAD 128
#define FFDIM 1536
#define QKVN 3072
#define LN_EPS 1e-5f
#define ATT_SCALE 0.08838834764831845f   /* 128^-0.5 */

/* ------------------------------------------------------------------ */
/* Scratch (device globals: allocation inside kernel_launch is banned) */
/* ------------------------------------------------------------------ */
__device__ __half g_xcat [(size_t)MTOK * 1024];   /* fp16 concat (GEMM A)  */
__device__ float  g_xfull[(size_t)MTOK * 1024];   /* residual (full fp32)  */
__device__ __half g_xtf  [(size_t)MTOK * 1024];   /* fp16 xfull (GEMM A)   */
__device__ __half g_qkvh [(size_t)MTOK * 3072];   /* qkv fp16              */
__device__ float  g_obuf [(size_t)MTOK * 1024];
__device__ __half g_ybuf [(size_t)MTOK * 1024];   /* post-LN fp16          */
__device__ __half g_hbuf [(size_t)MTOK * 1536];   /* FFN hidden fp16       */
/* transposed fp16 weights [N, K] */
__device__ __half g_wt_emb[(size_t)EMBN * 1024];
__device__ __half g_wt_qkv[(size_t)QKVN * 1024];
__device__ __half g_wt_1  [(size_t)FFDIM * 1024];
__device__ __half g_wt_2  [(size_t)PDIM * FFDIM];

/* ------------------------------------------------------------------ */
__device__ __forceinline__ uint32_t smem_u32(const void* p) {
    uint32_t a;
    asm("{ .reg .u64 t; cvta.to.shared.u64 t, %1; cvt.u32.u64 %0, t; }"
        : "=r"(a) : "l"(p));
    return a;
}

__device__ __forceinline__ void cp16(uint32_t saddr, const void* gptr) {
    asm volatile("cp.async.cg.shared.global [%0], [%1], 16;"
                 :: "r"(saddr), "l"(gptr));
}
#define CP_COMMIT() asm volatile("cp.async.commit_group;" ::: "memory")
#define CP_WAIT2()  asm volatile("cp.async.wait_group 2;" ::: "memory")

__device__ __forceinline__ void ldm_x4(uint32_t& r0, uint32_t& r1,
                                       uint32_t& r2, uint32_t& r3,
                                       uint32_t saddr) {
    asm volatile("ldmatrix.sync.aligned.m8n8.x4.shared.b16 {%0,%1,%2,%3}, [%4];"
                 : "=r"(r0), "=r"(r1), "=r"(r2), "=r"(r3) : "r"(saddr));
}

__device__ __forceinline__ void mma_f16(float* c, const uint32_t* a,
                                        const uint32_t* b) {
    asm volatile(
        "mma.sync.aligned.m16n8k16.row.col.f32.f16.f16.f32 "
        "{%0,%1,%2,%3}, {%4,%5,%6,%7}, {%8,%9}, {%0,%1,%2,%3};"
        : "+f"(c[0]), "+f"(c[1]), "+f"(c[2]), "+f"(c[3])
        : "r"(a[0]), "r"(a[1]), "r"(a[2]), "r"(a[3]),
          "r"(b[0]), "r"(b[1]));
}

__device__ __forceinline__ float gelu_f(float x) {
    float x3 = x * x * x;
    return 0.5f * x * (1.0f + tanhf(0.7978845608028654f * (x + 0.044715f * x3)));
}

/* ------------------------------------------------------------------ */
/* 32x32 transpose + fp16 convert: Wt[N,K] = half(W[K,N]^T)            */
/* ------------------------------------------------------------------ */
__global__ void transpose_kernel(const float* __restrict__ W,
                                 __half* __restrict__ Wt, int K, int N) {
    __shared__ float t[32][33];
    int k0 = blockIdx.y * 32, n0 = blockIdx.x * 32;
    int x = threadIdx.x, y = threadIdx.y;
#pragma unroll
    for (int i = y; i < 32; i += 8)
        t[i][x] = W[(size_t)(k0 + i) * N + n0 + x];
    __syncthreads();
#pragma unroll
    for (int i = y; i < 32; i += 8)
        Wt[(size_t)(n0 + i) * K + k0 + x] = __float2half_rn(t[x][i]);
}

/* ------------------------------------------------------------------ */
/* fp16 mma.sync GEMM, cp.async 3-stage pipeline, ldmatrix fragments.  */
/* C[M,N] = A[M,K] @ Bt[N,K]^T (+bias)(+gelu)                          */
/* block 128x128x32, 128 threads, 4 warps, warp tile 64x64             */
/* ------------------------------------------------------------------ */
#define BKH 40                        /* padded k-stride in halfs */
#define STG_BYTES (2 * 128 * BKH * 2) /* A+B one stage: 20480 B */
#define GEMM_SMEM_BYTES (3 * STG_BYTES)

template <bool GELU, bool HASBIAS, bool OUT_HALF, bool WRITE2>
__global__ __launch_bounds__(128)
void mma_gemm(const __half* __restrict__ A, const __half* __restrict__ Bt,
              const float* __restrict__ bias, void* __restrict__ Cv,
              __half* __restrict__ C2, int M, int N, int K, int ldc) {
    extern __shared__ uint32_t sm[];

    const int tid  = threadIdx.x;
    const int wid  = tid >> 5;
    const int lane = tid & 31;
    const int qr   = lane >> 2;      /* 0..7 */
    const int qc   = lane & 3;       /* 0..3 */
    const int bm0  = blockIdx.y * 128;
    const int bn0  = blockIdx.x * 128;
    const int m0   = (wid >> 1) * 64;   /* warp tile origin */
    const int n0   = (wid & 1) * 64;

    const uint32_t sbase = smem_u32(sm);

    /* per-thread ldmatrix base offsets (bytes within a stage) */
    const uint32_t a_ldm = (uint32_t)((m0 + (lane & 15)) * BKH
                                      + (lane >> 4) * 8) * 2u;
    const uint32_t b_ldm = (uint32_t)(128 * BKH * 2)
        + (uint32_t)((n0 + (lane & 7) + ((lane & 16) ? 8 : 0)) * BKH
                     + ((lane & 8) ? 8 : 0)) * 2u;

    float acc[4][8][4];
#pragma unroll
    for (int mt = 0; mt < 4; mt++)
#pragma unroll
        for (int nt = 0; nt < 8; nt++)
#pragma unroll
            for (int r = 0; r < 4; r++) acc[mt][nt][r] = 0.0f;

    const int nk = K >> 5;

    /* cp.async one k-tile (A 128x32h, B 128x32h) into stage s */
    auto issue = [&](int s, int kt) {
        uint32_t aoff = sbase + (uint32_t)(s * STG_BYTES);
        uint32_t boff = aoff + (uint32_t)(128 * BKH * 2);
        int k0 = kt << 5;
#pragma unroll
        for (int t = 0; t < 4; t++) {
            int chunk = t * 128 + tid;        /* 0..511 */
            int row   = chunk >> 2;
            int ch    = (chunk & 3) << 3;     /* half offset in row: 0,8,16,24 */
            uint32_t so = (uint32_t)(row * BKH + ch) * 2u;
            cp16(aoff + so, A  + (size_t)(bm0 + row) * K + k0 + ch);
            cp16(boff + so, Bt + (size_t)(bn0 + row) * K + k0 + ch);
        }
    };

    issue(0, 0); CP_COMMIT();
    issue(1, 1); CP_COMMIT();
    issue(2, 2); CP_COMMIT();

    for (int i = 0; i < nk; i++) {
        CP_WAIT2();
        __syncthreads();

        const int s = i % 3;
        const uint32_t stg = sbase + (uint32_t)(s * STG_BYTES);

#pragma unroll
        for (int ks = 0; ks < 2; ks++) {           /* two k16 steps */
            const uint32_t kb = (uint32_t)(ks * 16 * 2);   /* 16 halfs */
            uint32_t afr[4][4], bfr[8][2];
#pragma unroll
            for (int mt = 0; mt < 4; mt++)
                ldm_x4(afr[mt][0], afr[mt][1], afr[mt][2], afr[mt][3],
                       stg + a_ldm + kb + (uint32_t)(mt * 16 * BKH * 2));
#pragma unroll
            for (int p = 0; p < 4; p++)
                ldm_x4(bfr[2 * p][0], bfr[2 * p][1],
                       bfr[2 * p + 1][0], bfr[2 * p + 1][1],
                       stg + b_ldm + kb + (uint32_t)(p * 16 * BKH * 2));
#pragma unroll
            for (int mt = 0; mt < 4; mt++)
#pragma unroll
                for (int nt = 0; nt < 8; nt++)
                    mma_f16(acc[mt][nt], afr[mt], bfr[nt]);
        }

        __syncthreads();
        if (i + 3 < nk) issue(s, i + 3);
        CP_COMMIT();
    }

    /* epilogue */
    float*  Cf = (float*)Cv;
    __half* Ch = (__half*)Cv;
#pragma unroll
    for (int mt = 0; mt < 4; mt++) {
        int r0 = bm0 + m0 + mt * 16 + qr;
#pragma unroll
        for (int nt = 0; nt < 8; nt++) {
            int c0 = bn0 + n0 + nt * 8 + qc * 2;
            float v0 = acc[mt][nt][0], v1 = acc[mt][nt][1];
            float v2 = acc[mt][nt][2], v3 = acc[mt][nt][3];
            if (HASBIAS) {
                float bb0 = bias[c0], bb1 = bias[c0 + 1];
                v0 += bb0; v1 += bb1; v2 += bb0; v3 += bb1;
            }
            if (GELU) {
                v0 = gelu_f(v0); v1 = gelu_f(v1);
                v2 = gelu_f(v2); v3 = gelu_f(v3);
            }
            if (OUT_HALF) {
                *(half2*)(Ch + (size_t)r0 * ldc + c0)       = __floats2half2_rn(v0, v1);
                *(half2*)(Ch + (size_t)(r0 + 8) * ldc + c0) = __floats2half2_rn(v2, v3);
            } else {
                float2 p0; p0.x = v0; p0.y = v1;
                float2 p1; p1.x = v2; p1.y = v3;
                *(float2*)(Cf + (size_t)r0 * ldc + c0)       = p0;
                *(float2*)(Cf + (size_t)(r0 + 8) * ldc + c0) = p1;
            }
            if (WRITE2) {
                *(half2*)(C2 + (size_t)r0 * ldc + c0)       = __floats2half2_rn(v0, v1);
                *(half2*)(C2 + (size_t)(r0 + 8) * ldc + c0) = __floats2half2_rn(v2, v3);
            }
        }
    }
}

/* ------------------------------------------------------------------ */
/* concat(x1,x2) -> xcat (fp16)                                        */
/* ------------------------------------------------------------------ */
__global__ void concat_kernel(const float* __restrict__ x1,
                              const float* __restrict__ x2,
                              __half* __restrict__ xcat) {
    size_t i4 = (size_t)blockIdx.x * blockDim.x + threadIdx.x;
    if (i4 >= (size_t)MTOK * 256) return;
    size_t m  = i4 >> 8;
    int    c4 = (int)(i4 & 255) * 4;
    float4 v;
    if (c4 < CIN) v = *(const float4*)(x1 + m * CIN + c4);
    else          v = *(const float4*)(x2 + m * CIN + (c4 - CIN));
    half2 h0 = __floats2half2_rn(v.x, v.y);
    half2 h1 = __floats2half2_rn(v.z, v.w);
    half2* dst = (half2*)(xcat + m * 1024 + c4);
    dst[0] = h0; dst[1] = h1;
}

/* pos -> xfull[:,768:] (fp32) and xtf[:,768:] (fp16) */
__global__ void posfill_kernel(const float* __restrict__ pos,
                               float* __restrict__ xfull,
                               __half* __restrict__ xtf) {
    size_t i4 = (size_t)blockIdx.x * blockDim.x + threadIdx.x;
    if (i4 >= (size_t)MTOK * 64) return;
    size_t m  = i4 >> 6;
    int    c4 = (int)(i4 & 63) * 4;
    int    n  = (int)(m % SEQ);
    float4 v = *(const float4*)(pos + n * POSN + c4);
    *(float4*)(xfull + m * 1024 + EMBN + c4) = v;
    half2* dst = (half2*)(xtf + m * 1024 + EMBN + c4);
    dst[0] = __floats2half2_rn(v.x, v.y);
    dst[1] = __floats2half2_rn(v.z, v.w);
}

/* ------------------------------------------------------------------ */
/* Per (batch, head) attention, N=14, D=128, qkv in fp16               */
/* ------------------------------------------------------------------ */
__global__ __launch_bounds__(128)
void attn_kernel(const __half* __restrict__ qkv, const float* __restrict__ hr,
                 float* __restrict__ obuf) {
    int bh = blockIdx.x;
    int b  = bh >> 3;
    int h  = bh & 7;
    int d  = threadIdx.x;

    __shared__ float qs[SEQ * 129];
    __shared__ float ks[SEQ * 129];
    __shared__ float vs[SEQ * 128];
    __shared__ float att[SEQ * 16];

    const __half* base = qkv + (size_t)b * SEQ * QKVN;
    int hoff = h * DHEAD;
#pragma unroll
    for (int i = 0; i < SEQ; i++) {
        const __half* row = base + (size_t)i * QKVN;
        qs[i * 129 + d] = __half2float(row[hoff + d]);
        ks[i * 129 + d] = __half2float(row[PDIM + hoff + d]);
        vs[i * 128 + d] = __half2float(row[2 * PDIM + hoff + d]);
    }
    __syncthreads();

    for (int p = d; p < SEQ * SEQ; p += 128) {
        int i = p / SEQ, j = p % SEQ;
        float s = 0.0f;
#pragma unroll
        for (int dd = 0; dd < DHEAD; dd++)
            s += qs[i * 129 + dd] * ks[j * 129 + dd];
        att[i * 16 + j] = s * ATT_SCALE;
    }
    __syncthreads();

    if (d < SEQ) {
        int i = d;
        float mx = -1e30f;
#pragma unroll
        for (int j = 0; j < SEQ; j++) mx = fmaxf(mx, att[i * 16 + j]);
        float sum = 0.0f;
#pragma unroll
        for (int j = 0; j < SEQ; j++) {
            float e = expf(att[i * 16 + j] - mx);
            att[i * 16 + j] = e;
            sum += e;
        }
        float inv = 1.0f / sum;
        const float* hrp = hr + ((size_t)b * SEQ + i) * SEQ;
#pragma unroll
        for (int j = 0; j < SEQ; j++) att[i * 16 + j] *= inv * hrp[j];
    }
    __syncthreads();

#pragma unroll
    for (int i = 0; i < SEQ; i++) {
        float s = 0.0f;
#pragma unroll
        for (int j = 0; j < SEQ; j++) s += att[i * 16 + j] * vs[j * 128 + d];
        obuf[((size_t)b * SEQ + i) * PDIM + hoff + d] = s;
    }
}

/* ------------------------------------------------------------------ */
/* ybuf = half(LayerNorm(o + res) * g + b)                             */
/* ------------------------------------------------------------------ */
__global__ __launch_bounds__(256)
void add_ln_kernel(const float* __restrict__ o, const float* __restrict__ res,
                   const float* __restrict__ gam, const float* __restrict__ bet,
                   __half* __restrict__ y) {
    int m   = blockIdx.x;
    int tid = threadIdx.x;
    const float* op = o   + (size_t)m * PDIM;
    const float* rp = res + (size_t)m * PDIM;

    float v[4];
    float s = 0.0f, ss = 0.0f;
#pragma unroll
    for (int t = 0; t < 4; t++) {
        int c = tid + t * 256;
        float x = op[c] + rp[c];
        v[t] = x;
        s  += x;
        ss += x * x;
    }
#pragma unroll
    for (int off = 16; off; off >>= 1) {
        s  += __shfl_down_sync(0xFFFFFFFFu, s,  off);
        ss += __shfl_down_sync(0xFFFFFFFFu, ss, off);
    }
    __shared__ float ws[8], wss[8], s_mu, s_inv;
    if ((tid & 31) == 0) { ws[tid >> 5] = s; wss[tid >> 5] = ss; }
    __syncthreads();
    if (tid == 0) {
        float ts = 0.0f, tss = 0.0f;
#pragma unroll
        for (int w = 0; w < 8; w++) { ts += ws[w]; tss += wss[w]; }
        float mu  = ts * (1.0f / PDIM);
        float var = tss * (1.0f / PDIM) - mu * mu;
        s_mu  = mu;
        s_inv = rsqrtf(var + LN_EPS);
    }
    __syncthreads();
    float mu = s_mu, inv = s_inv;
    __half* yp = y + (size_t)m * PDIM;
#pragma unroll
    for (int t = 0; t < 4; t++) {
        int c = tid + t * 256;
        yp[c] = __float2half_rn((v[t] - mu) * inv * gam[c] + bet[c]);
    }
}

/* ------------------------------------------------------------------ */
extern "C" void kernel_launch(void* const* d_in, const int* in_sizes, int n_in,
                              void* d_out, int out_size) {
    const float* x1    = (const float*)d_in[0];
    const float* x2    = (const float*)d_in[1];
    const float* hr    = (const float*)d_in[2];
    const float* W_emb = (const float*)d_in[3];
    const float* b_emb = (const float*)d_in[4];
    const float* pos   = (const float*)d_in[5];
    const float* W_qkv = (const float*)d_in[6];
    const float* ln_g  = (const float*)d_in[7];
    const float* ln_b  = (const float*)d_in[8];
    const float* W1    = (const float*)d_in[9];
    const float* b1    = (const float*)d_in[10];
    const float* W2    = (const float*)d_in[11];
    const float* b2    = (const float*)d_in[12];
    float* out = (float*)d_out;

    void* p;
    __half *xcat, *xtf, *qkvh, *ybuf, *hbuf;
    float  *xfull, *obuf;
    __half *wt_emb, *wt_qkv, *wt_1, *wt_2;
    cudaGetSymbolAddress(&p, g_xcat);   xcat   = (__half*)p;
    cudaGetSymbolAddress(&p, g_xfull);  xfull  = (float*)p;
    cudaGetSymbolAddress(&p, g_xtf);    xtf    = (__half*)p;
    cudaGetSymbolAddress(&p, g_qkvh);   qkvh   = (__half*)p;
    cudaGetSymbolAddress(&p, g_obuf);   obuf   = (float*)p;
    cudaGetSymbolAddress(&p, g_ybuf);   ybuf   = (__half*)p;
    cudaGetSymbolAddress(&p, g_hbuf);   hbuf   = (__half*)p;
    cudaGetSymbolAddress(&p, g_wt_emb); wt_emb = (__half*)p;
    cudaGetSymbolAddress(&p, g_wt_qkv); wt_qkv = (__half*)p;
    cudaGetSymbolAddress(&p, g_wt_1);   wt_1   = (__half*)p;
    cudaGetSymbolAddress(&p, g_wt_2);   wt_2   = (__half*)p;

    cudaFuncSetAttribute(mma_gemm<false, true,  false, true >,
                         cudaFuncAttributeMaxDynamicSharedMemorySize, GEMM_SMEM_BYTES);
    cudaFuncSetAttribute(mma_gemm<false, false, true,  false>,
                         cudaFuncAttributeMaxDynamicSharedMemorySize, GEMM_SMEM_BYTES);
    cudaFuncSetAttribute(mma_gemm<true,  true,  true,  false>,
                         cudaFuncAttributeMaxDynamicSharedMemorySize, GEMM_SMEM_BYTES);
    cudaFuncSetAttribute(mma_gemm<false, true,  false, false>,
                         cudaFuncAttributeMaxDynamicSharedMemorySize, GEMM_SMEM_BYTES);

    /* 0. weight transposes + fp16 convert */
    {
        dim3 blk(32, 8);
        transpose_kernel<<<dim3(EMBN  / 32, 1024 / 32), blk>>>(W_emb, wt_emb, 1024, EMBN);
        transpose_kernel<<<dim3(QKVN  / 32, 1024 / 32), blk>>>(W_qkv, wt_qkv, 1024, QKVN);
        transpose_kernel<<<dim3(FFDIM / 32, 1024 / 32), blk>>>(W1,    wt_1,   1024, FFDIM);
        transpose_kernel<<<dim3(PDIM  / 32, FFDIM / 32), blk>>>(W2,   wt_2,   FFDIM, PDIM);
    }

    /* 1. concat(x1,x2) -> fp16 */
    {
        size_t tot = (size_t)MTOK * 256;
        concat_kernel<<<(unsigned)((tot + 255) / 256), 256>>>(x1, x2, xcat);
    }
    /* 2. emb GEMM -> xfull fp32 + xtf fp16 */
    {
        dim3 grid(EMBN / 128, MTOK / 128);
        mma_gemm<false, true, false, true><<<grid, 128, GEMM_SMEM_BYTES>>>(
            xcat, wt_emb, b_emb, xfull, xtf, MTOK, EMBN, 1024, PDIM);
    }
    /* 3. pos -> xfull/xtf [:, 768:] */
    {
        size_t tot = (size_t)MTOK * 64;
        posfill_kernel<<<(unsigned)((tot + 255) / 256), 256>>>(pos, xfull, xtf);
    }
    /* 4. qkv GEMM -> fp16 */
    {
        dim3 grid(QKVN / 128, MTOK / 128);
        mma_gemm<false, false, true, false><<<grid, 128, GEMM_SMEM_BYTES>>>(
            xtf, wt_qkv, nullptr, qkvh, nullptr, MTOK, QKVN, 1024, QKVN);
    }
    /* 5. attention (fp16 qkv in, fp32 out) */
    attn_kernel<<<BATCH * HEADS, 128>>>(qkvh, hr, obuf);

    /* 6. add-residual + LayerNorm -> fp16 */
    add_ln_kernel<<<MTOK, 256>>>(obuf, xfull, ln_g, ln_b, ybuf);

    /* 7. FFN1 (gelu) -> fp16 hbuf */
    {
        dim3 grid(FFDIM / 128, MTOK / 128);
        mma_gemm<true, true, true, false><<<grid, 128, GEMM_SMEM_BYTES>>>(
            ybuf, wt_1, b1, hbuf, nullptr, MTOK, FFDIM, 1024, FFDIM);
    }
    /* 8. FFN2 -> out fp32 */
    {
        dim3 grid(PDIM / 128, MTOK / 128);
        mma_gemm<false, true, false, false><<<grid, 128, GEMM_SMEM_BYTES>>>(
            hbuf, wt_2, b2, out, nullptr, MTOK, PDIM, FFDIM, PDIM);
    }
}

// round 16
// speedup vs baseline: 1.4082x; 1.4082x over previous
#include <cuda_runtime.h>
#include <cuda_fp16.h>
#include <math.h>
#include <stdint.h>

#define BATCH 4096
#define SEQ 14
#define MTOK (BATCH * SEQ)          /* 57344 tokens */
#define CIN 512
#define PDIM 1024
#define EMBN 768                    /* P - 256 */
#define POSN 256
#define HEADS 8
#define DHEAD 128
#define FFDIM 1536
#define QKVN 3072
#define LN_EPS 1e-5f
#define ATT_SCALE 0.08838834764831845f   /* 128^-0.5 */

/* ------------------------------------------------------------------ */
/* Scratch (device globals: allocation inside kernel_launch is banned) */
/* ------------------------------------------------------------------ */
__device__ __half g_xcat [(size_t)MTOK * 1024];   /* fp16 concat (GEMM A)  */
__device__ float  g_xfull[(size_t)MTOK * 1024];   /* residual (full fp32)  */
__device__ __half g_xtf  [(size_t)MTOK * 1024];   /* fp16 xfull (GEMM A)   */
__device__ __half g_qkvh [(size_t)MTOK * 3072];   /* qkv fp16              */
__device__ float  g_obuf [(size_t)MTOK * 1024];
__device__ __half g_ybuf [(size_t)MTOK * 1024];   /* post-LN fp16          */
__device__ __half g_hbuf [(size_t)MTOK * 1536];   /* FFN hidden fp16       */
/* transposed fp16 weights [N, K] */
__device__ __half g_wt_emb[(size_t)EMBN * 1024];
__device__ __half g_wt_qkv[(size_t)QKVN * 1024];
__device__ __half g_wt_1  [(size_t)FFDIM * 1024];
__device__ __half g_wt_2  [(size_t)PDIM * FFDIM];

/* ------------------------------------------------------------------ */
__device__ __forceinline__ uint32_t smem_u32(const void* p) {
    uint32_t a;
    asm("{ .reg .u64 t; cvta.to.shared.u64 t, %1; cvt.u32.u64 %0, t; }"
        : "=r"(a) : "l"(p));
    return a;
}

__device__ __forceinline__ void cp16(uint32_t saddr, const void* gptr) {
    asm volatile("cp.async.cg.shared.global [%0], [%1], 16;"
                 :: "r"(saddr), "l"(gptr));
}
#define CP_COMMIT() asm volatile("cp.async.commit_group;" ::: "memory")
#define CP_WAIT2()  asm volatile("cp.async.wait_group 2;" ::: "memory")

__device__ __forceinline__ void ldm_x4(uint32_t& r0, uint32_t& r1,
                                       uint32_t& r2, uint32_t& r3,
                                       uint32_t saddr) {
    asm volatile("ldmatrix.sync.aligned.m8n8.x4.shared.b16 {%0,%1,%2,%3}, [%4];"
                 : "=r"(r0), "=r"(r1), "=r"(r2), "=r"(r3) : "r"(saddr));
}

__device__ __forceinline__ void mma_f16(float* c, const uint32_t* a,
                                        const uint32_t* b) {
    asm volatile(
        "mma.sync.aligned.m16n8k16.row.col.f32.f16.f16.f32 "
        "{%0,%1,%2,%3}, {%4,%5,%6,%7}, {%8,%9}, {%0,%1,%2,%3};"
        : "+f"(c[0]), "+f"(c[1]), "+f"(c[2]), "+f"(c[3])
        : "r"(a[0]), "r"(a[1]), "r"(a[2]), "r"(a[3]),
          "r"(b[0]), "r"(b[1]));
}

__device__ __forceinline__ float gelu_f(float x) {
    float x3 = x * x * x;
    return 0.5f * x * (1.0f + tanhf(0.7978845608028654f * (x + 0.044715f * x3)));
}

/* ------------------------------------------------------------------ */
/* 32x32 transpose + fp16 convert: Wt[N,K] = half(W[K,N]^T)            */
/* ------------------------------------------------------------------ */
__global__ void transpose_kernel(const float* __restrict__ W,
                                 __half* __restrict__ Wt, int K, int N) {
    __shared__ float t[32][33];
    int k0 = blockIdx.y * 32, n0 = blockIdx.x * 32;
    int x = threadIdx.x, y = threadIdx.y;
#pragma unroll
    for (int i = y; i < 32; i += 8)
        t[i][x] = W[(size_t)(k0 + i) * N + n0 + x];
    __syncthreads();
#pragma unroll
    for (int i = y; i < 32; i += 8)
        Wt[(size_t)(n0 + i) * K + k0 + x] = __float2half_rn(t[x][i]);
}

/* ------------------------------------------------------------------ */
/* fp16 mma.sync GEMM, cp.async 4-stage pipeline, ldmatrix fragments.  */
/* ONE barrier per k-iteration (stage overwritten at iter i is the one */
/* read at iter i-1, protected by the iter-i barrier).                 */
/* C[M,N] = A[M,K] @ Bt[N,K]^T (+bias)(+gelu)                          */
/* block 128x128x32, 128 threads, 4 warps, warp tile 64x64             */
/* ------------------------------------------------------------------ */
#define BKH 40                        /* padded k-stride in halfs */
#define STG_BYTES (2 * 128 * BKH * 2) /* A+B one stage: 20480 B */
#define N_STG 4
#define GEMM_SMEM_BYTES (N_STG * STG_BYTES)   /* 81920 */

template <bool GELU, bool HASBIAS, bool OUT_HALF, bool WRITE2>
__global__ __launch_bounds__(128)
void mma_gemm(const __half* __restrict__ A, const __half* __restrict__ Bt,
              const float* __restrict__ bias, void* __restrict__ Cv,
              __half* __restrict__ C2, int M, int N, int K, int ldc) {
    extern __shared__ uint32_t sm[];

    const int tid  = threadIdx.x;
    const int wid  = tid >> 5;
    const int lane = tid & 31;
    const int qr   = lane >> 2;      /* 0..7 */
    const int qc   = lane & 3;       /* 0..3 */
    const int bm0  = blockIdx.y * 128;
    const int bn0  = blockIdx.x * 128;
    const int m0   = (wid >> 1) * 64;   /* warp tile origin */
    const int n0   = (wid & 1) * 64;

    const uint32_t sbase = smem_u32(sm);

    /* per-thread ldmatrix base offsets (bytes within a stage) */
    const uint32_t a_ldm = (uint32_t)((m0 + (lane & 15)) * BKH
                                      + (lane >> 4) * 8) * 2u;
    const uint32_t b_ldm = (uint32_t)(128 * BKH * 2)
        + (uint32_t)((n0 + (lane & 7) + ((lane & 16) ? 8 : 0)) * BKH
                     + ((lane & 8) ? 8 : 0)) * 2u;

    float acc[4][8][4];
#pragma unroll
    for (int mt = 0; mt < 4; mt++)
#pragma unroll
        for (int nt = 0; nt < 8; nt++)
#pragma unroll
            for (int r = 0; r < 4; r++) acc[mt][nt][r] = 0.0f;

    const int nk = K >> 5;

    /* cp.async one k-tile (A 128x32h, B 128x32h) into stage s */
    auto issue = [&](int s, int kt) {
        uint32_t aoff = sbase + (uint32_t)(s * STG_BYTES);
        uint32_t boff = aoff + (uint32_t)(128 * BKH * 2);
        int k0 = kt << 5;
#pragma unroll
        for (int t = 0; t < 4; t++) {
            int chunk = t * 128 + tid;        /* 0..511 */
            int row   = chunk >> 2;
            int ch    = (chunk & 3) << 3;     /* half offset in row: 0,8,16,24 */
            uint32_t so = (uint32_t)(row * BKH + ch) * 2u;
            cp16(aoff + so, A  + (size_t)(bm0 + row) * K + k0 + ch);
            cp16(boff + so, Bt + (size_t)(bn0 + row) * K + k0 + ch);
        }
    };

    issue(0, 0); CP_COMMIT();
    issue(1, 1); CP_COMMIT();
    issue(2, 2); CP_COMMIT();

    for (int i = 0; i < nk; i++) {
        CP_WAIT2();          /* tile i resident */
        __syncthreads();     /* also guards stage (i-1)%4 for re-issue below */

        const int s = i & 3;
        const uint32_t stg = sbase + (uint32_t)(s * STG_BYTES);

#pragma unroll
        for (int ks = 0; ks < 2; ks++) {           /* two k16 steps */
            const uint32_t kb = (uint32_t)(ks * 16 * 2);   /* 16 halfs */
            uint32_t afr[4][4], bfr[8][2];
#pragma unroll
            for (int mt = 0; mt < 4; mt++)
                ldm_x4(afr[mt][0], afr[mt][1], afr[mt][2], afr[mt][3],
                       stg + a_ldm + kb + (uint32_t)(mt * 16 * BKH * 2));
#pragma unroll
            for (int p = 0; p < 4; p++)
                ldm_x4(bfr[2 * p][0], bfr[2 * p][1],
                       bfr[2 * p + 1][0], bfr[2 * p + 1][1],
                       stg + b_ldm + kb + (uint32_t)(p * 16 * BKH * 2));
#pragma unroll
            for (int mt = 0; mt < 4; mt++)
#pragma unroll
                for (int nt = 0; nt < 8; nt++)
                    mma_f16(acc[mt][nt], afr[mt], bfr[nt]);
        }

        /* no second barrier: stage (i+3)&3 == (i-1)&3, readers done */
        if (i + 3 < nk) issue((i + 3) & 3, i + 3);
        CP_COMMIT();
    }

    /* epilogue */
    float*  Cf = (float*)Cv;
    __half* Ch = (__half*)Cv;
#pragma unroll
    for (int mt = 0; mt < 4; mt++) {
        int r0 = bm0 + m0 + mt * 16 + qr;
#pragma unroll
        for (int nt = 0; nt < 8; nt++) {
            int c0 = bn0 + n0 + nt * 8 + qc * 2;
            float v0 = acc[mt][nt][0], v1 = acc[mt][nt][1];
            float v2 = acc[mt][nt][2], v3 = acc[mt][nt][3];
            if (HASBIAS) {
                float bb0 = bias[c0], bb1 = bias[c0 + 1];
                v0 += bb0; v1 += bb1; v2 += bb0; v3 += bb1;
            }
            if (GELU) {
                v0 = gelu_f(v0); v1 = gelu_f(v1);
                v2 = gelu_f(v2); v3 = gelu_f(v3);
            }
            if (OUT_HALF) {
                *(half2*)(Ch + (size_t)r0 * ldc + c0)       = __floats2half2_rn(v0, v1);
                *(half2*)(Ch + (size_t)(r0 + 8) * ldc + c0) = __floats2half2_rn(v2, v3);
            } else {
                float2 p0; p0.x = v0; p0.y = v1;
                float2 p1; p1.x = v2; p1.y = v3;
                *(float2*)(Cf + (size_t)r0 * ldc + c0)       = p0;
                *(float2*)(Cf + (size_t)(r0 + 8) * ldc + c0) = p1;
            }
            if (WRITE2) {
                *(half2*)(C2 + (size_t)r0 * ldc + c0)       = __floats2half2_rn(v0, v1);
                *(half2*)(C2 + (size_t)(r0 + 8) * ldc + c0) = __floats2half2_rn(v2, v3);
            }
        }
    }
}

/* ------------------------------------------------------------------ */
/* concat(x1,x2) -> xcat (fp16)                                        */
/* ------------------------------------------------------------------ */
__global__ void concat_kernel(const float* __restrict__ x1,
                              const float* __restrict__ x2,
                              __half* __restrict__ xcat) {
    size_t i4 = (size_t)blockIdx.x * blockDim.x + threadIdx.x;
    if (i4 >= (size_t)MTOK * 256) return;
    size_t m  = i4 >> 8;
    int    c4 = (int)(i4 & 255) * 4;
    float4 v;
    if (c4 < CIN) v = *(const float4*)(x1 + m * CIN + c4);
    else          v = *(const float4*)(x2 + m * CIN + (c4 - CIN));
    half2 h0 = __floats2half2_rn(v.x, v.y);
    half2 h1 = __floats2half2_rn(v.z, v.w);
    half2* dst = (half2*)(xcat + m * 1024 + c4);
    dst[0] = h0; dst[1] = h1;
}

/* pos -> xfull[:,768:] (fp32) and xtf[:,768:] (fp16) */
__global__ void posfill_kernel(const float* __restrict__ pos,
                               float* __restrict__ xfull,
                               __half* __restrict__ xtf) {
    size_t i4 = (size_t)blockIdx.x * blockDim.x + threadIdx.x;
    if (i4 >= (size_t)MTOK * 64) return;
    size_t m  = i4 >> 6;
    int    c4 = (int)(i4 & 63) * 4;
    int    n  = (int)(m % SEQ);
    float4 v = *(const float4*)(pos + n * POSN + c4);
    *(float4*)(xfull + m * 1024 + EMBN + c4) = v;
    half2* dst = (half2*)(xtf + m * 1024 + EMBN + c4);
    dst[0] = __floats2half2_rn(v.x, v.y);
    dst[1] = __floats2half2_rn(v.z, v.w);
}

/* ------------------------------------------------------------------ */
/* Per (batch, head) attention, N=14, D=128, qkv in fp16               */
/* ------------------------------------------------------------------ */
__global__ __launch_bounds__(128)
void attn_kernel(const __half* __restrict__ qkv, const float* __restrict__ hr,
                 float* __restrict__ obuf) {
    int bh = blockIdx.x;
    int b  = bh >> 3;
    int h  = bh & 7;
    int d  = threadIdx.x;

    __shared__ float qs[SEQ * 129];
    __shared__ float ks[SEQ * 129];
    __shared__ float vs[SEQ * 128];
    __shared__ float att[SEQ * 16];

    const __half* base = qkv + (size_t)b * SEQ * QKVN;
    int hoff = h * DHEAD;
#pragma unroll
    for (int i = 0; i < SEQ; i++) {
        const __half* row = base + (size_t)i * QKVN;
        qs[i * 129 + d] = __half2float(row[hoff + d]);
        ks[i * 129 + d] = __half2float(row[PDIM + hoff + d]);
        vs[i * 128 + d] = __half2float(row[2 * PDIM + hoff + d]);
    }
    __syncthreads();

    for (int p = d; p < SEQ * SEQ; p += 128) {
        int i = p / SEQ, j = p % SEQ;
        float s = 0.0f;
#pragma unroll
        for (int dd = 0; dd < DHEAD; dd++)
            s += qs[i * 129 + dd] * ks[j * 129 + dd];
        att[i * 16 + j] = s * ATT_SCALE;
    }
    __syncthreads();

    if (d < SEQ) {
        int i = d;
        float mx = -1e30f;
#pragma unroll
        for (int j = 0; j < SEQ; j++) mx = fmaxf(mx, att[i * 16 + j]);
        float sum = 0.0f;
#pragma unroll
        for (int j = 0; j < SEQ; j++) {
            float e = expf(att[i * 16 + j] - mx);
            att[i * 16 + j] = e;
            sum += e;
        }
        float inv = 1.0f / sum;
        const float* hrp = hr + ((size_t)b * SEQ + i) * SEQ;
#pragma unroll
        for (int j = 0; j < SEQ; j++) att[i * 16 + j] *= inv * hrp[j];
    }
    __syncthreads();

#pragma unroll
    for (int i = 0; i < SEQ; i++) {
        float s = 0.0f;
#pragma unroll
        for (int j = 0; j < SEQ; j++) s += att[i * 16 + j] * vs[j * 128 + d];
        obuf[((size_t)b * SEQ + i) * PDIM + hoff + d] = s;
    }
}

/* ------------------------------------------------------------------ */
/* ybuf = half(LayerNorm(o + res) * g + b)                             */
/* ------------------------------------------------------------------ */
__global__ __launch_bounds__(256)
void add_ln_kernel(const float* __restrict__ o, const float* __restrict__ res,
                   const float* __restrict__ gam, const float* __restrict__ bet,
                   __half* __restrict__ y) {
    int m   = blockIdx.x;
    int tid = threadIdx.x;
    const float* op = o   + (size_t)m * PDIM;
    const float* rp = res + (size_t)m * PDIM;

    float v[4];
    float s = 0.0f, ss = 0.0f;
#pragma unroll
    for (int t = 0; t < 4; t++) {
        int c = tid + t * 256;
        float x = op[c] + rp[c];
        v[t] = x;
        s  += x;
        ss += x * x;
    }
#pragma unroll
    for (int off = 16; off; off >>= 1) {
        s  += __shfl_down_sync(0xFFFFFFFFu, s,  off);
        ss += __shfl_down_sync(0xFFFFFFFFu, ss, off);
    }
    __shared__ float ws[8], wss[8], s_mu, s_inv;
    if ((tid & 31) == 0) { ws[tid >> 5] = s; wss[tid >> 5] = ss; }
    __syncthreads();
    if (tid == 0) {
        float ts = 0.0f, tss = 0.0f;
#pragma unroll
        for (int w = 0; w < 8; w++) { ts += ws[w]; tss += wss[w]; }
        float mu  = ts * (1.0f / PDIM);
        float var = tss * (1.0f / PDIM) - mu * mu;
        s_mu  = mu;
        s_inv = rsqrtf(var + LN_EPS);
    }
    __syncthreads();
    float mu = s_mu, inv = s_inv;
    __half* yp = y + (size_t)m * PDIM;
#pragma unroll
    for (int t = 0; t < 4; t++) {
        int c = tid + t * 256;
        yp[c] = __float2half_rn((v[t] - mu) * inv * gam[c] + bet[c]);
    }
}

/* ------------------------------------------------------------------ */
extern "C" void kernel_launch(void* const* d_in, const int* in_sizes, int n_in,
                              void* d_out, int out_size) {
    const float* x1    = (const float*)d_in[0];
    const float* x2    = (const float*)d_in[1];
    const float* hr    = (const float*)d_in[2];
    const float* W_emb = (const float*)d_in[3];
    const float* b_emb = (const float*)d_in[4];
    const float* pos   = (const float*)d_in[5];
    const float* W_qkv = (const float*)d_in[6];
    const float* ln_g  = (const float*)d_in[7];
    const float* ln_b  = (const float*)d_in[8];
    const float* W1    = (const float*)d_in[9];
    const float* b1    = (const float*)d_in[10];
    const float* W2    = (const float*)d_in[11];
    const float* b2    = (const float*)d_in[12];
    float* out = (float*)d_out;

    void* p;
    __half *xcat, *xtf, *qkvh, *ybuf, *hbuf;
    float  *xfull, *obuf;
    __half *wt_emb, *wt_qkv, *wt_1, *wt_2;
    cudaGetSymbolAddress(&p, g_xcat);   xcat   = (__half*)p;
    cudaGetSymbolAddress(&p, g_xfull);  xfull  = (float*)p;
    cudaGetSymbolAddress(&p, g_xtf);    xtf    = (__half*)p;
    cudaGetSymbolAddress(&p, g_qkvh);   qkvh   = (__half*)p;
    cudaGetSymbolAddress(&p, g_obuf);   obuf   = (float*)p;
    cudaGetSymbolAddress(&p, g_ybuf);   ybuf   = (__half*)p;
    cudaGetSymbolAddress(&p, g_hbuf);   hbuf   = (__half*)p;
    cudaGetSymbolAddress(&p, g_wt_emb); wt_emb = (__half*)p;
    cudaGetSymbolAddress(&p, g_wt_qkv); wt_qkv = (__half*)p;
    cudaGetSymbolAddress(&p, g_wt_1);   wt_1   = (__half*)p;
    cudaGetSymbolAddress(&p, g_wt_2);   wt_2   = (__half*)p;

    cudaFuncSetAttribute(mma_gemm<false, true,  false, true >,
                         cudaFuncAttributeMaxDynamicSharedMemorySize, GEMM_SMEM_BYTES);
    cudaFuncSetAttribute(mma_gemm<false, false, true,  false>,
                         cudaFuncAttributeMaxDynamicSharedMemorySize, GEMM_SMEM_BYTES);
    cudaFuncSetAttribute(mma_gemm<true,  true,  true,  false>,
                         cudaFuncAttributeMaxDynamicSharedMemorySize, GEMM_SMEM_BYTES);
    cudaFuncSetAttribute(mma_gemm<false, true,  false, false>,
                         cudaFuncAttributeMaxDynamicSharedMemorySize, GEMM_SMEM_BYTES);

    /* 0. weight transposes + fp16 convert */
    {
        dim3 blk(32, 8);
        transpose_kernel<<<dim3(EMBN  / 32, 1024 / 32), blk>>>(W_emb, wt_emb, 1024, EMBN);
        transpose_kernel<<<dim3(QKVN  / 32, 1024 / 32), blk>>>(W_qkv, wt_qkv, 1024, QKVN);
        transpose_kernel<<<dim3(FFDIM / 32, 1024 / 32), blk>>>(W1,    wt_1,   1024, FFDIM);
        transpose_kernel<<<dim3(PDIM  / 32, FFDIM / 32), blk>>>(W2,   wt_2,   FFDIM, PDIM);
    }

    /* 1. concat(x1,x2) -> fp16 */
    {
        size_t tot = (size_t)MTOK * 256;
        concat_kernel<<<(unsigned)((tot + 255) / 256), 256>>>(x1, x2, xcat);
    }
    /* 2. emb GEMM -> xfull fp32 + xtf fp16 */
    {
        dim3 grid(EMBN / 128, MTOK / 128);
        mma_gemm<false, true, false, true><<<grid, 128, GEMM_SMEM_BYTES>>>(
            xcat, wt_emb, b_emb, xfull, xtf, MTOK, EMBN, 1024, PDIM);
    }
    /* 3. pos -> xfull/xtf [:, 768:] */
    {
        size_t tot = (size_t)MTOK * 64;
        posfill_kernel<<<(unsigned)((tot + 255) / 256), 256>>>(pos, xfull, xtf);
    }
    /* 4. qkv GEMM -> fp16 */
    {
        dim3 grid(QKVN / 128, MTOK / 128);
        mma_gemm<false, false, true, false><<<grid, 128, GEMM_SMEM_BYTES>>>(
            xtf, wt_qkv, nullptr, qkvh, nullptr, MTOK, QKVN, 1024, QKVN);
    }
    /* 5. attention (fp16 qkv in, fp32 out) */
    attn_kernel<<<BATCH * HEADS, 128>>>(qkvh, hr, obuf);

    /* 6. add-residual + LayerNorm -> fp16 */
    add_ln_kernel<<<MTOK, 256>>>(obuf, xfull, ln_g, ln_b, ybuf);

    /* 7. FFN1 (gelu) -> fp16 hbuf */
    {
        dim3 grid(FFDIM / 128, MTOK / 128);
        mma_gemm<true, true, true, false><<<grid, 128, GEMM_SMEM_BYTES>>>(
            ybuf, wt_1, b1, hbuf, nullptr, MTOK, FFDIM, 1024, FFDIM);
    }
    /* 8. FFN2 -> out fp32 */
    {
        dim3 grid(PDIM / 128, MTOK / 128);
        mma_gemm<false, true, false, false><<<grid, 128, GEMM_SMEM_BYTES>>>(
            hbuf, wt_2, b2, out, nullptr, MTOK, PDIM, FFDIM, PDIM);
    }
}

// round 17
// speedup vs baseline: 1.5432x; 1.0959x over previous
#include <cuda_runtime.h>
#include <cuda_fp16.h>
#include <math.h>
#include <stdint.h>

#define BATCH 4096
#define SEQ 14
#define MTOK (BATCH * SEQ)          /* 57344 tokens */
#define CIN 512
#define PDIM 1024
#define EMBN 768                    /* P - 256 */
#define POSN 256
#define HEADS 8
#define DHEAD 128
#define FFDIM 1536
#define QKVN 3072
#define LN_EPS 1e-5f
#define ATT_SCALE 0.08838834764831845f   /* 128^-0.5 */

/* ------------------------------------------------------------------ */
/* Scratch (device globals: allocation inside kernel_launch is banned) */
/* ------------------------------------------------------------------ */
__device__ __half g_xcat [(size_t)MTOK * 1024];   /* fp16 concat (GEMM A)  */
__device__ float  g_xfull[(size_t)MTOK * 1024];   /* residual (full fp32)  */
__device__ __half g_xtf  [(size_t)MTOK * 1024];   /* fp16 xfull (GEMM A)   */
__device__ __half g_qkvh [(size_t)MTOK * 3072];   /* qkv fp16              */
__device__ float  g_obuf [(size_t)MTOK * 1024];
__device__ __half g_ybuf [(size_t)MTOK * 1024];   /* post-LN fp16          */
__device__ __half g_hbuf [(size_t)MTOK * 1536];   /* FFN hidden fp16       */
/* transposed fp16 weights [N, K] */
__device__ __half g_wt_emb[(size_t)EMBN * 1024];
__device__ __half g_wt_qkv[(size_t)QKVN * 1024];
__device__ __half g_wt_1  [(size_t)FFDIM * 1024];
__device__ __half g_wt_2  [(size_t)PDIM * FFDIM];

/* ------------------------------------------------------------------ */
__device__ __forceinline__ uint32_t smem_u32(const void* p) {
    uint32_t a;
    asm("{ .reg .u64 t; cvta.to.shared.u64 t, %1; cvt.u32.u64 %0, t; }"
        : "=r"(a) : "l"(p));
    return a;
}

__device__ __forceinline__ void cp16(uint32_t saddr, const void* gptr) {
    asm volatile("cp.async.cg.shared.global [%0], [%1], 16;"
                 :: "r"(saddr), "l"(gptr));
}
#define CP_COMMIT() asm volatile("cp.async.commit_group;" ::: "memory")
#define CP_WAIT2()  asm volatile("cp.async.wait_group 2;" ::: "memory")

__device__ __forceinline__ void ldm_x4(uint32_t& r0, uint32_t& r1,
                                       uint32_t& r2, uint32_t& r3,
                                       uint32_t saddr) {
    asm volatile("ldmatrix.sync.aligned.m8n8.x4.shared.b16 {%0,%1,%2,%3}, [%4];"
                 : "=r"(r0), "=r"(r1), "=r"(r2), "=r"(r3) : "r"(saddr));
}

__device__ __forceinline__ void mma_f16(float* c, const uint32_t* a,
                                        const uint32_t* b) {
    asm volatile(
        "mma.sync.aligned.m16n8k16.row.col.f32.f16.f16.f32 "
        "{%0,%1,%2,%3}, {%4,%5,%6,%7}, {%8,%9}, {%0,%1,%2,%3};"
        : "+f"(c[0]), "+f"(c[1]), "+f"(c[2]), "+f"(c[3])
        : "r"(a[0]), "r"(a[1]), "r"(a[2]), "r"(a[3]),
          "r"(b[0]), "r"(b[1]));
}

__device__ __forceinline__ float gelu_f(float x) {
    float x3 = x * x * x;
    return 0.5f * x * (1.0f + tanhf(0.7978845608028654f * (x + 0.044715f * x3)));
}

/* ------------------------------------------------------------------ */
/* 32x32 transpose + fp16 convert: Wt[N,K] = half(W[K,N]^T)            */
/* ------------------------------------------------------------------ */
__global__ void transpose_kernel(const float* __restrict__ W,
                                 __half* __restrict__ Wt, int K, int N) {
    __shared__ float t[32][33];
    int k0 = blockIdx.y * 32, n0 = blockIdx.x * 32;
    int x = threadIdx.x, y = threadIdx.y;
#pragma unroll
    for (int i = y; i < 32; i += 8)
        t[i][x] = W[(size_t)(k0 + i) * N + n0 + x];
    __syncthreads();
#pragma unroll
    for (int i = y; i < 32; i += 8)
        Wt[(size_t)(n0 + i) * K + k0 + x] = __float2half_rn(t[x][i]);
}

/* ------------------------------------------------------------------ */
/* fp16 mma.sync GEMM, cp.async 3-stage pipeline, ldmatrix fragments.  */
/* C[M,N] = A[M,K] @ Bt[N,K]^T (+bias)(+gelu)                          */
/* block 128x128x32, 128 threads, 4 warps, warp tile 64x64             */
/* (exact R9 loop structure: 3 stages, two barriers per k-iteration)   */
/* ------------------------------------------------------------------ */
#define BKH 40                        /* padded k-stride in halfs */
#define STG_BYTES (2 * 128 * BKH * 2) /* A+B one stage: 20480 B */
#define GEMM_SMEM_BYTES (3 * STG_BYTES)

template <bool GELU, bool HASBIAS, bool OUT_HALF, bool WRITE2>
__global__ __launch_bounds__(128)
void mma_gemm(const __half* __restrict__ A, const __half* __restrict__ Bt,
              const float* __restrict__ bias, void* __restrict__ Cv,
              __half* __restrict__ C2, int M, int N, int K, int ldc) {
    extern __shared__ uint32_t sm[];

    const int tid  = threadIdx.x;
    const int wid  = tid >> 5;
    const int lane = tid & 31;
    const int qr   = lane >> 2;      /* 0..7 */
    const int qc   = lane & 3;       /* 0..3 */
    const int bm0  = blockIdx.y * 128;
    const int bn0  = blockIdx.x * 128;
    const int m0   = (wid >> 1) * 64;   /* warp tile origin */
    const int n0   = (wid & 1) * 64;

    const uint32_t sbase = smem_u32(sm);

    /* per-thread ldmatrix base offsets (bytes within a stage) */
    const uint32_t a_ldm = (uint32_t)((m0 + (lane & 15)) * BKH
                                      + (lane >> 4) * 8) * 2u;
    const uint32_t b_ldm = (uint32_t)(128 * BKH * 2)
        + (uint32_t)((n0 + (lane & 7) + ((lane & 16) ? 8 : 0)) * BKH
                     + ((lane & 8) ? 8 : 0)) * 2u;

    float acc[4][8][4];
#pragma unroll
    for (int mt = 0; mt < 4; mt++)
#pragma unroll
        for (int nt = 0; nt < 8; nt++)
#pragma unroll
            for (int r = 0; r < 4; r++) acc[mt][nt][r] = 0.0f;

    const int nk = K >> 5;

    /* cp.async one k-tile (A 128x32h, B 128x32h) into stage s */
    auto issue = [&](int s, int kt) {
        uint32_t aoff = sbase + (uint32_t)(s * STG_BYTES);
        uint32_t boff = aoff + (uint32_t)(128 * BKH * 2);
        int k0 = kt << 5;
#pragma unroll
        for (int t = 0; t < 4; t++) {
            int chunk = t * 128 + tid;        /* 0..511 */
            int row   = chunk >> 2;
            int ch    = (chunk & 3) << 3;     /* half offset in row: 0,8,16,24 */
            uint32_t so = (uint32_t)(row * BKH + ch) * 2u;
            cp16(aoff + so, A  + (size_t)(bm0 + row) * K + k0 + ch);
            cp16(boff + so, Bt + (size_t)(bn0 + row) * K + k0 + ch);
        }
    };

    issue(0, 0); CP_COMMIT();
    issue(1, 1); CP_COMMIT();
    issue(2, 2); CP_COMMIT();

    for (int i = 0; i < nk; i++) {
        CP_WAIT2();
        __syncthreads();

        const int s = i % 3;
        const uint32_t stg = sbase + (uint32_t)(s * STG_BYTES);

#pragma unroll
        for (int ks = 0; ks < 2; ks++) {           /* two k16 steps */
            const uint32_t kb = (uint32_t)(ks * 16 * 2);   /* 16 halfs */
            uint32_t afr[4][4], bfr[8][2];
#pragma unroll
            for (int mt = 0; mt < 4; mt++)
                ldm_x4(afr[mt][0], afr[mt][1], afr[mt][2], afr[mt][3],
                       stg + a_ldm + kb + (uint32_t)(mt * 16 * BKH * 2));
#pragma unroll
            for (int p = 0; p < 4; p++)
                ldm_x4(bfr[2 * p][0], bfr[2 * p][1],
                       bfr[2 * p + 1][0], bfr[2 * p + 1][1],
                       stg + b_ldm + kb + (uint32_t)(p * 16 * BKH * 2));
#pragma unroll
            for (int mt = 0; mt < 4; mt++)
#pragma unroll
                for (int nt = 0; nt < 8; nt++)
                    mma_f16(acc[mt][nt], afr[mt], bfr[nt]);
        }

        __syncthreads();
        if (i + 3 < nk) issue(s, i + 3);
        CP_COMMIT();
    }

    /* epilogue */
    float*  Cf = (float*)Cv;
    __half* Ch = (__half*)Cv;
#pragma unroll
    for (int mt = 0; mt < 4; mt++) {
        int r0 = bm0 + m0 + mt * 16 + qr;
#pragma unroll
        for (int nt = 0; nt < 8; nt++) {
            int c0 = bn0 + n0 + nt * 8 + qc * 2;
            float v0 = acc[mt][nt][0], v1 = acc[mt][nt][1];
            float v2 = acc[mt][nt][2], v3 = acc[mt][nt][3];
            if (HASBIAS) {
                float bb0 = bias[c0], bb1 = bias[c0 + 1];
                v0 += bb0; v1 += bb1; v2 += bb0; v3 += bb1;
            }
            if (GELU) {
                v0 = gelu_f(v0); v1 = gelu_f(v1);
                v2 = gelu_f(v2); v3 = gelu_f(v3);
            }
            if (OUT_HALF) {
                *(half2*)(Ch + (size_t)r0 * ldc + c0)       = __floats2half2_rn(v0, v1);
                *(half2*)(Ch + (size_t)(r0 + 8) * ldc + c0) = __floats2half2_rn(v2, v3);
            } else {
                float2 p0; p0.x = v0; p0.y = v1;
                float2 p1; p1.x = v2; p1.y = v3;
                *(float2*)(Cf + (size_t)r0 * ldc + c0)       = p0;
                *(float2*)(Cf + (size_t)(r0 + 8) * ldc + c0) = p1;
            }
            if (WRITE2) {
                *(half2*)(C2 + (size_t)r0 * ldc + c0)       = __floats2half2_rn(v0, v1);
                *(half2*)(C2 + (size_t)(r0 + 8) * ldc + c0) = __floats2half2_rn(v2, v3);
            }
        }
    }
}

/* ------------------------------------------------------------------ */
/* concat(x1,x2) -> xcat (fp16)                                        */
/* ------------------------------------------------------------------ */
__global__ void concat_kernel(const float* __restrict__ x1,
                              const float* __restrict__ x2,
                              __half* __restrict__ xcat) {
    size_t i4 = (size_t)blockIdx.x * blockDim.x + threadIdx.x;
    if (i4 >= (size_t)MTOK * 256) return;
    size_t m  = i4 >> 8;
    int    c4 = (int)(i4 & 255) * 4;
    float4 v;
    if (c4 < CIN) v = *(const float4*)(x1 + m * CIN + c4);
    else          v = *(const float4*)(x2 + m * CIN + (c4 - CIN));
    half2 h0 = __floats2half2_rn(v.x, v.y);
    half2 h1 = __floats2half2_rn(v.z, v.w);
    half2* dst = (half2*)(xcat + m * 1024 + c4);
    dst[0] = h0; dst[1] = h1;
}

/* pos -> xfull[:,768:] (fp32) and xtf[:,768:] (fp16) */
__global__ void posfill_kernel(const float* __restrict__ pos,
                               float* __restrict__ xfull,
                               __half* __restrict__ xtf) {
    size_t i4 = (size_t)blockIdx.x * blockDim.x + threadIdx.x;
    if (i4 >= (size_t)MTOK * 64) return;
    size_t m  = i4 >> 6;
    int    c4 = (int)(i4 & 63) * 4;
    int    n  = (int)(m % SEQ);
    float4 v = *(const float4*)(pos + n * POSN + c4);
    *(float4*)(xfull + m * 1024 + EMBN + c4) = v;
    half2* dst = (half2*)(xtf + m * 1024 + EMBN + c4);
    dst[0] = __floats2half2_rn(v.x, v.y);
    dst[1] = __floats2half2_rn(v.z, v.w);
}

/* ------------------------------------------------------------------ */
/* Per (batch, head) attention, N=14, D=128, qkv in fp16               */
/* ------------------------------------------------------------------ */
__global__ __launch_bounds__(128)
void attn_kernel(const __half* __restrict__ qkv, const float* __restrict__ hr,
                 float* __restrict__ obuf) {
    int bh = blockIdx.x;
    int b  = bh >> 3;
    int h  = bh & 7;
    int d  = threadIdx.x;

    __shared__ float qs[SEQ * 129];
    __shared__ float ks[SEQ * 129];
    __shared__ float vs[SEQ * 128];
    __shared__ float att[SEQ * 16];

    const __half* base = qkv + (size_t)b * SEQ * QKVN;
    int hoff = h * DHEAD;
#pragma unroll
    for (int i = 0; i < SEQ; i++) {
        const __half* row = base + (size_t)i * QKVN;
        qs[i * 129 + d] = __half2float(row[hoff + d]);
        ks[i * 129 + d] = __half2float(row[PDIM + hoff + d]);
        vs[i * 128 + d] = __half2float(row[2 * PDIM + hoff + d]);
    }
    __syncthreads();

    for (int p = d; p < SEQ * SEQ; p += 128) {
        int i = p / SEQ, j = p % SEQ;
        float s = 0.0f;
#pragma unroll
        for (int dd = 0; dd < DHEAD; dd++)
            s += qs[i * 129 + dd] * ks[j * 129 + dd];
        att[i * 16 + j] = s * ATT_SCALE;
    }
    __syncthreads();

    if (d < SEQ) {
        int i = d;
        float mx = -1e30f;
#pragma unroll
        for (int j = 0; j < SEQ; j++) mx = fmaxf(mx, att[i * 16 + j]);
        float sum = 0.0f;
#pragma unroll
        for (int j = 0; j < SEQ; j++) {
            float e = expf(att[i * 16 + j] - mx);
            att[i * 16 + j] = e;
            sum += e;
        }
        float inv = 1.0f / sum;
        const float* hrp = hr + ((size_t)b * SEQ + i) * SEQ;
#pragma unroll
        for (int j = 0; j < SEQ; j++) att[i * 16 + j] *= inv * hrp[j];
    }
    __syncthreads();

#pragma unroll
    for (int i = 0; i < SEQ; i++) {
        float s = 0.0f;
#pragma unroll
        for (int j = 0; j < SEQ; j++) s += att[i * 16 + j] * vs[j * 128 + d];
        obuf[((size_t)b * SEQ + i) * PDIM + hoff + d] = s;
    }
}

/* ------------------------------------------------------------------ */
/* ybuf = half(LayerNorm(o + res) * g + b)                             */
/* ------------------------------------------------------------------ */
__global__ __launch_bounds__(256)
void add_ln_kernel(const float* __restrict__ o, const float* __restrict__ res,
                   const float* __restrict__ gam, const float* __restrict__ bet,
                   __half* __restrict__ y) {
    int m   = blockIdx.x;
    int tid = threadIdx.x;
    const float* op = o   + (size_t)m * PDIM;
    const float* rp = res + (size_t)m * PDIM;

    float v[4];
    float s = 0.0f, ss = 0.0f;
#pragma unroll
    for (int t = 0; t < 4; t++) {
        int c = tid + t * 256;
        float x = op[c] + rp[c];
        v[t] = x;
        s  += x;
        ss += x * x;
    }
#pragma unroll
    for (int off = 16; off; off >>= 1) {
        s  += __shfl_down_sync(0xFFFFFFFFu, s,  off);
        ss += __shfl_down_sync(0xFFFFFFFFu, ss, off);
    }
    __shared__ float ws[8], wss[8], s_mu, s_inv;
    if ((tid & 31) == 0) { ws[tid >> 5] = s; wss[tid >> 5] = ss; }
    __syncthreads();
    if (tid == 0) {
        float ts = 0.0f, tss = 0.0f;
#pragma unroll
        for (int w = 0; w < 8; w++) { ts += ws[w]; tss += wss[w]; }
        float mu  = ts * (1.0f / PDIM);
        float var = tss * (1.0f / PDIM) - mu * mu;
        s_mu  = mu;
        s_inv = rsqrtf(var + LN_EPS);
    }
    __syncthreads();
    float mu = s_mu, inv = s_inv;
    __half* yp = y + (size_t)m * PDIM;
#pragma unroll
    for (int t = 0; t < 4; t++) {
        int c = tid + t * 256;
        yp[c] = __float2half_rn((v[t] - mu) * inv * gam[c] + bet[c]);
    }
}

/* ------------------------------------------------------------------ */
extern "C" void kernel_launch(void* const* d_in, const int* in_sizes, int n_in,
                              void* d_out, int out_size) {
    const float* x1    = (const float*)d_in[0];
    const float* x2    = (const float*)d_in[1];
    const float* hr    = (const float*)d_in[2];
    const float* W_emb = (const float*)d_in[3];
    const float* b_emb = (const float*)d_in[4];
    const float* pos   = (const float*)d_in[5];
    const float* W_qkv = (const float*)d_in[6];
    const float* ln_g  = (const float*)d_in[7];
    const float* ln_b  = (const float*)d_in[8];
    const float* W1    = (const float*)d_in[9];
    const float* b1    = (const float*)d_in[10];
    const float* W2    = (const float*)d_in[11];
    const float* b2    = (const float*)d_in[12];
    float* out = (float*)d_out;

    void* p;
    __half *xcat, *xtf, *qkvh, *ybuf, *hbuf;
    float  *xfull, *obuf;
    __half *wt_emb, *wt_qkv, *wt_1, *wt_2;
    cudaGetSymbolAddress(&p, g_xcat);   xcat   = (__half*)p;
    cudaGetSymbolAddress(&p, g_xfull);  xfull  = (float*)p;
    cudaGetSymbolAddress(&p, g_xtf);    xtf    = (__half*)p;
    cudaGetSymbolAddress(&p, g_qkvh);   qkvh   = (__half*)p;
    cudaGetSymbolAddress(&p, g_obuf);   obuf   = (float*)p;
    cudaGetSymbolAddress(&p, g_ybuf);   ybuf   = (__half*)p;
    cudaGetSymbolAddress(&p, g_hbuf);   hbuf   = (__half*)p;
    cudaGetSymbolAddress(&p, g_wt_emb); wt_emb = (__half*)p;
    cudaGetSymbolAddress(&p, g_wt_qkv); wt_qkv = (__half*)p;
    cudaGetSymbolAddress(&p, g_wt_1);   wt_1   = (__half*)p;
    cudaGetSymbolAddress(&p, g_wt_2);   wt_2   = (__half*)p;

    cudaFuncSetAttribute(mma_gemm<false, true,  false, true >,
                         cudaFuncAttributeMaxDynamicSharedMemorySize, GEMM_SMEM_BYTES);
    cudaFuncSetAttribute(mma_gemm<false, false, true,  false>,
                         cudaFuncAttributeMaxDynamicSharedMemorySize, GEMM_SMEM_BYTES);
    cudaFuncSetAttribute(mma_gemm<true,  true,  true,  false>,
                         cudaFuncAttributeMaxDynamicSharedMemorySize, GEMM_SMEM_BYTES);
    cudaFuncSetAttribute(mma_gemm<false, true,  false, false>,
                         cudaFuncAttributeMaxDynamicSharedMemorySize, GEMM_SMEM_BYTES);

    /* 0. weight transposes + fp16 convert */
    {
        dim3 blk(32, 8);
        transpose_kernel<<<dim3(EMBN  / 32, 1024 / 32), blk>>>(W_emb, wt_emb, 1024, EMBN);
        transpose_kernel<<<dim3(QKVN  / 32, 1024 / 32), blk>>>(W_qkv, wt_qkv, 1024, QKVN);
        transpose_kernel<<<dim3(FFDIM / 32, 1024 / 32), blk>>>(W1,    wt_1,   1024, FFDIM);
        transpose_kernel<<<dim3(PDIM  / 32, FFDIM / 32), blk>>>(W2,   wt_2,   FFDIM, PDIM);
    }

    /* 1. concat(x1,x2) -> fp16 */
    {
        size_t tot = (size_t)MTOK * 256;
        concat_kernel<<<(unsigned)((tot + 255) / 256), 256>>>(x1, x2, xcat);
    }
    /* 2. emb GEMM -> xfull fp32 + xtf fp16 */
    {
        dim3 grid(EMBN / 128, MTOK / 128);
        mma_gemm<false, true, false, true><<<grid, 128, GEMM_SMEM_BYTES>>>(
            xcat, wt_emb, b_emb, xfull, xtf, MTOK, EMBN, 1024, PDIM);
    }
    /* 3. pos -> xfull/xtf [:, 768:] */
    {
        size_t tot = (size_t)MTOK * 64;
        posfill_kernel<<<(unsigned)((tot + 255) / 256), 256>>>(pos, xfull, xtf);
    }
    /* 4. qkv GEMM -> fp16 */
    {
        dim3 grid(QKVN / 128, MTOK / 128);
        mma_gemm<false, false, true, false><<<grid, 128, GEMM_SMEM_BYTES>>>(
            xtf, wt_qkv, nullptr, qkvh, nullptr, MTOK, QKVN, 1024, QKVN);
    }
    /* 5. attention (fp16 qkv in, fp32 out) */
    attn_kernel<<<BATCH * HEADS, 128>>>(qkvh, hr, obuf);

    /* 6. add-residual + LayerNorm -> fp16 */
    add_ln_kernel<<<MTOK, 256>>>(obuf, xfull, ln_g, ln_b, ybuf);

    /* 7. FFN1 (gelu) -> fp16 hbuf */
    {
        dim3 grid(FFDIM / 128, MTOK / 128);
        mma_gemm<true, true, true, false><<<grid, 128, GEMM_SMEM_BYTES>>>(
            ybuf, wt_1, b1, hbuf, nullptr, MTOK, FFDIM, 1024, FFDIM);
    }
    /* 8. FFN2 -> out fp32 */
    {
        dim3 grid(PDIM / 128, MTOK / 128);
        mma_gemm<false, true, false, false><<<grid, 128, GEMM_SMEM_BYTES>>>(
            hbuf, wt_2, b2, out, nullptr, MTOK, PDIM, FFDIM, PDIM);
    }
}